// round 1
// baseline (speedup 1.0000x reference)
#include <cuda_runtime.h>
#include <cstdio>

// ---------------------------------------------------------------------------
// SDNE graph autoencoder: 4x GraphConv (PyG semantics) + leaky_relu(0.01)
//   layer: out = segment_sum(h[src] -> dst) @ Wrel^T + b + h @ Wroot^T
// Linearity trick: aggregate in min(d_in, d_out) dimension.
//   L0: 128->256  aggregate input  (128)
//   L1: 256->64   aggregate output (64)   -> emb
//   L2: 64->256   aggregate input  (64)
//   L3: 256->128  aggregate output (128)  -> h_final
// Output layout: [ h_final (N*128) | emb (N*64) ]
// ---------------------------------------------------------------------------

#define NMAX 50000
#define LEAKY 0.01f

// scratch (device globals: no allocation allowed)
__device__ float g_buf1[(size_t)NMAX * 256];
__device__ float g_buf2[(size_t)NMAX * 256];
__device__ float g_t   [(size_t)NMAX * 128];
__device__ float g_s   [(size_t)NMAX * 128];
__device__ float g_agg [(size_t)NMAX * 128];
__device__ float g_emb [(size_t)NMAX * 64];
__device__ int   g_is64;

// ---------------------------------------------------------------------------
// Detect whether edge_index is stored as int64 or int32.
// Values are node ids in [0, 50000): if int64, every high 32-bit word is 0.
// ---------------------------------------------------------------------------
__global__ void detect_idx64(const unsigned int* __restrict__ w, int npairs) {
    unsigned int any = 0;
    for (int k = threadIdx.x; k < npairs; k += blockDim.x)
        any |= w[2 * k + 1];
    unsigned int anynz = __syncthreads_or(any != 0u);
    if (threadIdx.x == 0) g_is64 = anynz ? 0 : 1;
}

__global__ void zero_kernel(float* __restrict__ p, long long n) {
    long long i = (long long)blockIdx.x * blockDim.x + threadIdx.x;
    long long stride = (long long)gridDim.x * blockDim.x;
    for (; i < n; i += stride) p[i] = 0.0f;
}

// one warp per edge: agg[dst] += feat[src]
__global__ void scatter_add_kernel(float* __restrict__ agg,
                                   const float* __restrict__ feat,
                                   const void* __restrict__ eidx,
                                   int E, int D) {
    int warp = (int)((blockIdx.x * (long long)blockDim.x + threadIdx.x) >> 5);
    int lane = threadIdx.x & 31;
    if (warp >= E) return;
    long long src, dst;
    if (g_is64) {
        const long long* p = (const long long*)eidx;
        src = p[warp]; dst = p[E + warp];
    } else {
        const int* p = (const int*)eidx;
        src = p[warp]; dst = p[E + warp];
    }
    const float* fs = feat + src * D;
    float*       ad = agg  + dst * D;
    for (int j = lane; j < D; j += 32)
        atomicAdd(ad + j, fs[j]);
}

// out = leaky(agg + s + b[col]),  n = N*D, D power of two (mask = D-1)
__global__ void combine_kernel(const float* __restrict__ agg,
                               const float* __restrict__ s,
                               const float* __restrict__ b,
                               float* __restrict__ out,
                               long long n, int mask) {
    long long i = (long long)blockIdx.x * blockDim.x + threadIdx.x;
    if (i >= n) return;
    float v = agg[i] + s[i] + b[(int)(i & mask)];
    out[i] = (v > 0.0f) ? v : LEAKY * v;
}

// ---------------------------------------------------------------------------
// Tiled fp32 GEMM: C[M, DOUT] = A[M, K] @ W[DOUT, K]^T
//   FUSE:  C = leaky(acc + C_old + bias[col])   (second pass of fused layer)
//   !FUSE: C = acc
// 64x64 tile, 256 threads, 4x4 per thread, BK=16. K in {64,128,256}.
// ---------------------------------------------------------------------------
template <int K, bool FUSE>
__global__ void gemm64(const float* __restrict__ A,
                       const float* __restrict__ W,
                       const float* __restrict__ bias,
                       float* __restrict__ C,
                       int M, int DOUT) {
    __shared__ float As[16][68];
    __shared__ float Ws[16][68];

    const int tid  = threadIdx.x;
    const int row0 = blockIdx.x * 64;
    const int col0 = blockIdx.y * 64;

    const int lr = tid >> 2;        // 0..63 (tile row for loads)
    const int lc = (tid & 3) * 4;   // 0,4,8,12 (k offset for loads)

    const bool arow_ok = (row0 + lr) < M;
    const float* Aptr = A + (size_t)(row0 + lr) * K + lc;
    const float* Wptr = W + (size_t)(col0 + lr) * K + lc;

    const int ty = tid >> 4;        // 0..15
    const int tx = tid & 15;        // 0..15

    float acc[4][4];
#pragma unroll
    for (int i = 0; i < 4; i++)
#pragma unroll
        for (int j = 0; j < 4; j++) acc[i][j] = 0.0f;

#pragma unroll
    for (int k0 = 0; k0 < K; k0 += 16) {
        float4 av = arow_ok ? *(const float4*)(Aptr + k0)
                            : make_float4(0.f, 0.f, 0.f, 0.f);
        float4 wv = *(const float4*)(Wptr + k0);
        As[lc + 0][lr] = av.x; As[lc + 1][lr] = av.y;
        As[lc + 2][lr] = av.z; As[lc + 3][lr] = av.w;
        Ws[lc + 0][lr] = wv.x; Ws[lc + 1][lr] = wv.y;
        Ws[lc + 2][lr] = wv.z; Ws[lc + 3][lr] = wv.w;
        __syncthreads();

#pragma unroll
        for (int kk = 0; kk < 16; kk++) {
            float a0 = As[kk][ty * 4 + 0];
            float a1 = As[kk][ty * 4 + 1];
            float a2 = As[kk][ty * 4 + 2];
            float a3 = As[kk][ty * 4 + 3];
            float w0 = Ws[kk][tx * 4 + 0];
            float w1 = Ws[kk][tx * 4 + 1];
            float w2 = Ws[kk][tx * 4 + 2];
            float w3 = Ws[kk][tx * 4 + 3];
            acc[0][0] += a0 * w0; acc[0][1] += a0 * w1; acc[0][2] += a0 * w2; acc[0][3] += a0 * w3;
            acc[1][0] += a1 * w0; acc[1][1] += a1 * w1; acc[1][2] += a1 * w2; acc[1][3] += a1 * w3;
            acc[2][0] += a2 * w0; acc[2][1] += a2 * w1; acc[2][2] += a2 * w2; acc[2][3] += a2 * w3;
            acc[3][0] += a3 * w0; acc[3][1] += a3 * w1; acc[3][2] += a3 * w2; acc[3][3] += a3 * w3;
        }
        __syncthreads();
    }

    const int colb = col0 + tx * 4;
#pragma unroll
    for (int i = 0; i < 4; i++) {
        int row = row0 + ty * 4 + i;
        if (row >= M) continue;
        float* crow = C + (size_t)row * DOUT + colb;
        if (FUSE) {
            float4 cold = *(const float4*)crow;
            const float* bp = bias + colb;
            float v0 = acc[i][0] + cold.x + bp[0];
            float v1 = acc[i][1] + cold.y + bp[1];
            float v2 = acc[i][2] + cold.z + bp[2];
            float v3 = acc[i][3] + cold.w + bp[3];
            float4 r;
            r.x = (v0 > 0.f) ? v0 : LEAKY * v0;
            r.y = (v1 > 0.f) ? v1 : LEAKY * v1;
            r.z = (v2 > 0.f) ? v2 : LEAKY * v2;
            r.w = (v3 > 0.f) ? v3 : LEAKY * v3;
            *(float4*)crow = r;
        } else {
            float4 r = make_float4(acc[i][0], acc[i][1], acc[i][2], acc[i][3]);
            *(float4*)crow = r;
        }
    }
}

// ---------------------------------------------------------------------------
static void launch_gemm(int K, bool fuse, const float* A, const float* W,
                        const float* b, float* C, int M, int D) {
    dim3 grid((M + 63) / 64, D / 64);
    dim3 blk(256);
    if (K == 64) {
        if (fuse) gemm64<64, true ><<<grid, blk>>>(A, W, b, C, M, D);
        else      gemm64<64, false><<<grid, blk>>>(A, W, b, C, M, D);
    } else if (K == 128) {
        if (fuse) gemm64<128, true ><<<grid, blk>>>(A, W, b, C, M, D);
        else      gemm64<128, false><<<grid, blk>>>(A, W, b, C, M, D);
    } else {
        if (fuse) gemm64<256, true ><<<grid, blk>>>(A, W, b, C, M, D);
        else      gemm64<256, false><<<grid, blk>>>(A, W, b, C, M, D);
    }
}

static void launch_zero(float* p, long long n) {
    int blocks = (int)((n + 255) / 256);
    if (blocks > 4096) blocks = 4096;
    zero_kernel<<<blocks, 256>>>(p, n);
}

static void launch_scatter(float* agg, const float* feat, const void* eidx,
                           int E, int D) {
    // one warp per edge, 8 warps per block
    int blocks = (E + 7) / 8;
    scatter_add_kernel<<<blocks, 256>>>(agg, feat, eidx, E, D);
}

static void launch_combine(const float* agg, const float* s, const float* b,
                           float* out, long long n, int D) {
    int blocks = (int)((n + 255) / 256);
    combine_kernel<<<blocks, 256>>>(agg, s, b, out, n, D - 1);
}

extern "C" void kernel_launch(void* const* d_in, const int* in_sizes, int n_in,
                              void* d_out, int out_size) {
    const float* x     = (const float*)d_in[0];
    const void*  eidx  = d_in[1];
    const float* Wrel0 = (const float*)d_in[2];
    const float* Wroot0= (const float*)d_in[3];
    const float* b0    = (const float*)d_in[4];
    const float* Wrel1 = (const float*)d_in[5];
    const float* Wroot1= (const float*)d_in[6];
    const float* b1    = (const float*)d_in[7];
    const float* Wrel2 = (const float*)d_in[8];
    const float* Wroot2= (const float*)d_in[9];
    const float* b2    = (const float*)d_in[10];
    const float* Wrel3 = (const float*)d_in[11];
    const float* Wroot3= (const float*)d_in[12];
    const float* b3    = (const float*)d_in[13];

    const int N = in_sizes[0] / 128;
    const int E = in_sizes[1] / 2;
    float* out = (float*)d_out;

    float *buf1, *buf2, *t, *s, *agg, *embS;
    cudaGetSymbolAddress((void**)&buf1, g_buf1);
    cudaGetSymbolAddress((void**)&buf2, g_buf2);
    cudaGetSymbolAddress((void**)&t,    g_t);
    cudaGetSymbolAddress((void**)&s,    g_s);
    cudaGetSymbolAddress((void**)&agg,  g_agg);
    cudaGetSymbolAddress((void**)&embS, g_emb);

    // emb goes directly into the output tail if it fits, else to scratch
    float* emb = ((long long)out_size >= (long long)N * 192)
                     ? out + (size_t)N * 128 : embS;

    int npairs = E < 4096 ? E : 4096;
    detect_idx64<<<1, 256>>>((const unsigned int*)eidx, npairs);

    // ---- Layer 0: 128 -> 256 (aggregate input) ----
    launch_zero(agg, (long long)N * 128);
    launch_scatter(agg, x, eidx, E, 128);
    launch_gemm(128, false, agg, Wrel0,  nullptr, buf1, N, 256);
    launch_gemm(128, true,  x,   Wroot0, b0,      buf1, N, 256);

    // ---- Layer 1: 256 -> 64 (aggregate output) -> emb ----
    launch_gemm(256, false, buf1, Wrel1,  nullptr, t, N, 64);
    launch_gemm(256, false, buf1, Wroot1, nullptr, s, N, 64);
    launch_zero(agg, (long long)N * 64);
    launch_scatter(agg, t, eidx, E, 64);
    launch_combine(agg, s, b1, emb, (long long)N * 64, 64);

    // ---- Layer 2: 64 -> 256 (aggregate input) ----
    launch_zero(agg, (long long)N * 64);
    launch_scatter(agg, emb, eidx, E, 64);
    launch_gemm(64, false, agg, Wrel2,  nullptr, buf2, N, 256);
    launch_gemm(64, true,  emb, Wroot2, b2,      buf2, N, 256);

    // ---- Layer 3: 256 -> 128 (aggregate output) -> h_final ----
    launch_gemm(256, false, buf2, Wrel3,  nullptr, t, N, 128);
    launch_gemm(256, false, buf2, Wroot3, nullptr, s, N, 128);
    launch_zero(agg, (long long)N * 128);
    launch_scatter(agg, t, eidx, E, 128);
    launch_combine(agg, s, b3, out, (long long)N * 128, 128);
}

// round 3
// speedup vs baseline: 1.2287x; 1.2287x over previous
#include <cuda_runtime.h>
#include <cuda_bf16.h>
#include <cstdint>

// ---------------------------------------------------------------------------
// SDNE graph autoencoder: 4x GraphConv (PyG) + leaky_relu(0.01).
//   layer: out = segsum(h[src]->dst) @ Wrel^T + b + h @ Wroot^T
// Linearity: aggregate in min(d_in, d_out) dim.
// GEMM engine: mma.sync m16n8k16 bf16, fp32 = hi+lo bf16 split,
//   D += Ah*Bh + Ah*Bl + Al*Bh  (fp32 accumulators; error ~2^-18)
// ---------------------------------------------------------------------------

#define NMAX 50000
#define LEAKY 0.01f

// scratch (device globals: no allocation allowed)
__device__ float g_buf1[(size_t)NMAX * 256];
__device__ float g_buf2[(size_t)NMAX * 256];
__device__ float g_t   [(size_t)NMAX * 128];
__device__ float g_s   [(size_t)NMAX * 128];
__device__ float g_agg [(size_t)NMAX * 128];
__device__ float g_emb [(size_t)NMAX * 64];
__device__ int   g_is64;

// --------------------------- helpers ---------------------------------------
__device__ __forceinline__ uint32_t smem_to_u32(const void* p) {
    uint32_t a;
    asm("{ .reg .u64 t; cvta.to.shared.u64 t, %1; cvt.u32.u64 %0, t; }"
        : "=r"(a) : "l"(p));
    return a;
}

#define LDSM4(r, addr) \
    asm volatile("ldmatrix.sync.aligned.m8n8.x4.shared.b16 {%0,%1,%2,%3}, [%4];" \
        : "=r"((r)[0]), "=r"((r)[1]), "=r"((r)[2]), "=r"((r)[3]) : "r"(addr))

#define MMA_BF16(c, a, b0r, b1r) \
    asm volatile("mma.sync.aligned.m16n8k16.row.col.f32.bf16.bf16.f32 " \
        "{%0,%1,%2,%3}, {%4,%5,%6,%7}, {%8,%9}, {%0,%1,%2,%3};" \
        : "+f"((c)[0]), "+f"((c)[1]), "+f"((c)[2]), "+f"((c)[3]) \
        : "r"((a)[0]), "r"((a)[1]), "r"((a)[2]), "r"((a)[3]), \
          "r"(b0r), "r"(b1r))

__device__ __forceinline__ void split2(float v0, float v1,
                                       uint32_t& h, uint32_t& l) {
    __nv_bfloat16 h0 = __float2bfloat16(v0), h1 = __float2bfloat16(v1);
    float r0 = v0 - __bfloat162float(h0);
    float r1 = v1 - __bfloat162float(h1);
    __nv_bfloat162 hh = __halves2bfloat162(h0, h1);
    __nv_bfloat162 ll = __halves2bfloat162(__float2bfloat16(r0),
                                           __float2bfloat16(r1));
    h = *(uint32_t*)&hh;
    l = *(uint32_t*)&ll;
}

// split 8 fp32 (two float4) into packed bf16 hi/lo uint4
__device__ __forceinline__ void split8(float4 a, float4 b, uint4& h, uint4& l) {
    split2(a.x, a.y, h.x, l.x);
    split2(a.z, a.w, h.y, l.y);
    split2(b.x, b.y, h.z, l.z);
    split2(b.z, b.w, h.w, l.w);
}

// --------------------------- small kernels ---------------------------------
__global__ void detect_idx64(const unsigned int* __restrict__ w, int npairs) {
    unsigned int any = 0;
    for (int k = threadIdx.x; k < npairs; k += blockDim.x)
        any |= w[2 * k + 1];
    unsigned int anynz = __syncthreads_or(any != 0u);
    if (threadIdx.x == 0) g_is64 = anynz ? 0 : 1;
}

__global__ void zero_kernel(float* __restrict__ p, long long n) {
    long long i = (long long)blockIdx.x * blockDim.x + threadIdx.x;
    long long stride = (long long)gridDim.x * blockDim.x;
    for (; i < n; i += stride) p[i] = 0.0f;
}

// one warp per edge: agg[dst] += feat[src]
__global__ void scatter_add_kernel(float* __restrict__ agg,
                                   const float* __restrict__ feat,
                                   const void* __restrict__ eidx,
                                   int E, int D) {
    int warp = (int)((blockIdx.x * (long long)blockDim.x + threadIdx.x) >> 5);
    int lane = threadIdx.x & 31;
    if (warp >= E) return;
    long long src, dst;
    if (g_is64) {
        const long long* p = (const long long*)eidx;
        src = p[warp]; dst = p[E + warp];
    } else {
        const int* p = (const int*)eidx;
        src = p[warp]; dst = p[E + warp];
    }
    const float* fs = feat + src * D;
    float*       ad = agg  + dst * D;
    for (int j = lane; j < D; j += 32)
        atomicAdd(ad + j, fs[j]);
}

// out = leaky(agg + s + b[col]),  n = N*D, D power of two (mask = D-1)
__global__ void combine_kernel(const float* __restrict__ agg,
                               const float* __restrict__ s,
                               const float* __restrict__ b,
                               float* __restrict__ out,
                               long long n, int mask) {
    long long i = (long long)blockIdx.x * blockDim.x + threadIdx.x;
    if (i >= n) return;
    float v = agg[i] + s[i] + b[(int)(i & mask)];
    out[i] = (v > 0.0f) ? v : LEAKY * v;
}

// ---------------------------------------------------------------------------
// mma.sync bf16-split GEMM: C[M, DOUT] = A[M, K] @ W[DOUT, K]^T
//   FUSE:  C = leaky(acc + C_old + bias[col])
//   !FUSE: C = acc
// Block: 256 threads (8 warps, 4(M) x 2(N)), tile 128(M) x 64(N), BK = 64.
// smem tiles bf16 hi/lo, 128B rows, chunk^(row&7) swizzle (ldmatrix
// conflict-free). Warp tile 32x32 via 2x4 m16n8k16 fragments, 3 MMA/pair.
// ---------------------------------------------------------------------------
template <int K, bool FUSE>
__global__ void __launch_bounds__(256) mma_gemm(const float* __restrict__ A,
                                                const float* __restrict__ W,
                                                const float* __restrict__ bias,
                                                float* __restrict__ C,
                                                int M, int DOUT) {
    __shared__ __align__(16) unsigned char sm[49152];
    const int AH = 0, AL = 16384, WH = 32768, WL = 40960;
    const uint32_t sb = smem_to_u32(sm);

    const int tid  = threadIdx.x;
    const int lane = tid & 31;
    const int wid  = tid >> 5;
    const int wm   = wid >> 1;      // 0..3  (M direction)
    const int wn   = wid & 1;       // 0..1  (N direction)
    const int row0 = blockIdx.x * 128;
    const int col0 = blockIdx.y * 64;

    float acc[2][4][4];
#pragma unroll
    for (int i = 0; i < 2; i++)
#pragma unroll
        for (int j = 0; j < 4; j++)
#pragma unroll
            for (int q = 0; q < 4; q++) acc[i][j][q] = 0.0f;

#pragma unroll
    for (int kc = 0; kc < K / 64; kc++) {
        const int kbase = kc * 64;

        // ---- A tile fill: 128 rows x 64 cols fp32 -> bf16 hi/lo ----
        {
            const int row  = tid >> 1;
            const int grow = row0 + row;
            const bool ok  = grow < M;
            const float* ap = A + (size_t)grow * K + kbase + (tid & 1) * 32;
            const int rx = row & 7;
#pragma unroll
            for (int i = 0; i < 4; i++) {
                const int chunk = ((tid & 1) << 2) + i;
                float4 v0 = ok ? *(const float4*)(ap + i * 8)
                               : make_float4(0.f, 0.f, 0.f, 0.f);
                float4 v1 = ok ? *(const float4*)(ap + i * 8 + 4)
                               : make_float4(0.f, 0.f, 0.f, 0.f);
                uint4 h, l;
                split8(v0, v1, h, l);
                const uint32_t off = row * 128 + ((chunk ^ rx) << 4);
                *(uint4*)(sm + AH + off) = h;
                *(uint4*)(sm + AL + off) = l;
            }
        }
        // ---- W tile fill: 64 rows x 64 cols ----
        {
#pragma unroll
            for (int j = 0; j < 2; j++) {
                const int task  = tid * 2 + j;     // 0..511
                const int row   = task >> 3;
                const int chunk = task & 7;
                const float* wp = W + (size_t)(col0 + row) * K + kbase + chunk * 8;
                float4 v0 = *(const float4*)(wp);
                float4 v1 = *(const float4*)(wp + 4);
                uint4 h, l;
                split8(v0, v1, h, l);
                const uint32_t off = row * 128 + ((chunk ^ (row & 7)) << 4);
                *(uint4*)(sm + WH + off) = h;
                *(uint4*)(sm + WL + off) = l;
            }
        }
        __syncthreads();

        // ---- compute: 4 k16 sub-steps ----
#pragma unroll
        for (int kk = 0; kk < 4; kk++) {
            uint32_t ah[2][4], al[2][4], bh[2][4], bl[2][4];
#pragma unroll
            for (int rb = 0; rb < 2; rb++) {
                const int row = wm * 32 + rb * 16 + (lane & 15);
                const int ch  = 2 * kk + (lane >> 4);
                const uint32_t ad = sb + AH + row * 128 +
                                    (((ch ^ (row & 7))) << 4);
                LDSM4(ah[rb], ad);
                LDSM4(al[rb], ad + 16384);
            }
#pragma unroll
            for (int q = 0; q < 2; q++) {
                const int sel  = lane >> 3;
                const int wrow = wn * 32 + q * 16 + ((sel >> 1) << 3) + (lane & 7);
                const int ch   = 2 * kk + (sel & 1);
                const uint32_t wd = sb + WH + wrow * 128 +
                                    ((ch ^ (wrow & 7)) << 4);
                LDSM4(bh[q], wd);
                LDSM4(bl[q], wd + 8192);
            }
#pragma unroll
            for (int rb = 0; rb < 2; rb++) {
#pragma unroll
                for (int nb = 0; nb < 4; nb++) {
                    const uint32_t b0h = bh[nb >> 1][(nb & 1) * 2];
                    const uint32_t b1h = bh[nb >> 1][(nb & 1) * 2 + 1];
                    const uint32_t b0l = bl[nb >> 1][(nb & 1) * 2];
                    const uint32_t b1l = bl[nb >> 1][(nb & 1) * 2 + 1];
                    MMA_BF16(acc[rb][nb], ah[rb], b0h, b1h);
                    MMA_BF16(acc[rb][nb], ah[rb], b0l, b1l);
                    MMA_BF16(acc[rb][nb], al[rb], b0h, b1h);
                }
            }
        }
        __syncthreads();
    }

    // ---- epilogue ----
    const int g  = lane >> 2;
    const int t4 = lane & 3;
#pragma unroll
    for (int rb = 0; rb < 2; rb++) {
        const int r1 = row0 + wm * 32 + rb * 16 + g;
        const int r2 = r1 + 8;
#pragma unroll
        for (int nb = 0; nb < 4; nb++) {
            const int col = col0 + wn * 32 + nb * 8 + t4 * 2;
            const float* ac = acc[rb][nb];
            if (FUSE) {
                const float bb0 = bias[col], bb1 = bias[col + 1];
                if (r1 < M) {
                    float* cp = C + (size_t)r1 * DOUT + col;
                    float2 o = *(const float2*)cp;
                    float v0 = ac[0] + o.x + bb0;
                    float v1 = ac[1] + o.y + bb1;
                    v0 = (v0 > 0.f) ? v0 : LEAKY * v0;
                    v1 = (v1 > 0.f) ? v1 : LEAKY * v1;
                    *(float2*)cp = make_float2(v0, v1);
                }
                if (r2 < M) {
                    float* cp = C + (size_t)r2 * DOUT + col;
                    float2 o = *(const float2*)cp;
                    float v0 = ac[2] + o.x + bb0;
                    float v1 = ac[3] + o.y + bb1;
                    v0 = (v0 > 0.f) ? v0 : LEAKY * v0;
                    v1 = (v1 > 0.f) ? v1 : LEAKY * v1;
                    *(float2*)cp = make_float2(v0, v1);
                }
            } else {
                if (r1 < M)
                    *(float2*)(C + (size_t)r1 * DOUT + col) =
                        make_float2(ac[0], ac[1]);
                if (r2 < M)
                    *(float2*)(C + (size_t)r2 * DOUT + col) =
                        make_float2(ac[2], ac[3]);
            }
        }
    }
}

// --------------------------- host side -------------------------------------
static void launch_gemm(int K, bool fuse, const float* A, const float* W,
                        const float* b, float* C, int M, int D) {
    dim3 grid((M + 127) / 128, D / 64);
    dim3 blk(256);
    if (K == 64) {
        if (fuse) mma_gemm<64, true ><<<grid, blk>>>(A, W, b, C, M, D);
        else      mma_gemm<64, false><<<grid, blk>>>(A, W, b, C, M, D);
    } else if (K == 128) {
        if (fuse) mma_gemm<128, true ><<<grid, blk>>>(A, W, b, C, M, D);
        else      mma_gemm<128, false><<<grid, blk>>>(A, W, b, C, M, D);
    } else {
        if (fuse) mma_gemm<256, true ><<<grid, blk>>>(A, W, b, C, M, D);
        else      mma_gemm<256, false><<<grid, blk>>>(A, W, b, C, M, D);
    }
}

static void launch_zero(float* p, long long n) {
    int blocks = (int)((n + 255) / 256);
    if (blocks > 4096) blocks = 4096;
    zero_kernel<<<blocks, 256>>>(p, n);
}

static void launch_scatter(float* agg, const float* feat, const void* eidx,
                           int E, int D) {
    int blocks = (E + 7) / 8;
    scatter_add_kernel<<<blocks, 256>>>(agg, feat, eidx, E, D);
}

static void launch_combine(const float* agg, const float* s, const float* b,
                           float* out, long long n, int D) {
    int blocks = (int)((n + 255) / 256);
    combine_kernel<<<blocks, 256>>>(agg, s, b, out, n, D - 1);
}

extern "C" void kernel_launch(void* const* d_in, const int* in_sizes, int n_in,
                              void* d_out, int out_size) {
    const float* x     = (const float*)d_in[0];
    const void*  eidx  = d_in[1];
    const float* Wrel0 = (const float*)d_in[2];
    const float* Wroot0= (const float*)d_in[3];
    const float* b0    = (const float*)d_in[4];
    const float* Wrel1 = (const float*)d_in[5];
    const float* Wroot1= (const float*)d_in[6];
    const float* b1    = (const float*)d_in[7];
    const float* Wrel2 = (const float*)d_in[8];
    const float* Wroot2= (const float*)d_in[9];
    const float* b2    = (const float*)d_in[10];
    const float* Wrel3 = (const float*)d_in[11];
    const float* Wroot3= (const float*)d_in[12];
    const float* b3    = (const float*)d_in[13];

    const int N = in_sizes[0] / 128;
    const int E = in_sizes[1] / 2;
    float* out = (float*)d_out;

    float *buf1, *buf2, *t, *s, *agg, *embS;
    cudaGetSymbolAddress((void**)&buf1, g_buf1);
    cudaGetSymbolAddress((void**)&buf2, g_buf2);
    cudaGetSymbolAddress((void**)&t,    g_t);
    cudaGetSymbolAddress((void**)&s,    g_s);
    cudaGetSymbolAddress((void**)&agg,  g_agg);
    cudaGetSymbolAddress((void**)&embS, g_emb);

    // emb goes directly into the output tail if it fits, else to scratch
    float* emb = ((long long)out_size >= (long long)N * 192)
                     ? out + (size_t)N * 128 : embS;

    int npairs = E < 4096 ? E : 4096;
    detect_idx64<<<1, 256>>>((const unsigned int*)eidx, npairs);

    // ---- Layer 0: 128 -> 256 (aggregate input) ----
    launch_zero(agg, (long long)N * 128);
    launch_scatter(agg, x, eidx, E, 128);
    launch_gemm(128, false, agg, Wrel0,  nullptr, buf1, N, 256);
    launch_gemm(128, true,  x,   Wroot0, b0,      buf1, N, 256);

    // ---- Layer 1: 256 -> 64 (aggregate output) -> emb ----
    launch_gemm(256, false, buf1, Wrel1,  nullptr, t, N, 64);
    launch_gemm(256, false, buf1, Wroot1, nullptr, s, N, 64);
    launch_zero(agg, (long long)N * 64);
    launch_scatter(agg, t, eidx, E, 64);
    launch_combine(agg, s, b1, emb, (long long)N * 64, 64);

    // ---- Layer 2: 64 -> 256 (aggregate input) ----
    launch_zero(agg, (long long)N * 64);
    launch_scatter(agg, emb, eidx, E, 64);
    launch_gemm(64, false, agg, Wrel2,  nullptr, buf2, N, 256);
    launch_gemm(64, true,  emb, Wroot2, b2,      buf2, N, 256);

    // ---- Layer 3: 256 -> 128 (aggregate output) -> h_final ----
    launch_gemm(256, false, buf2, Wrel3,  nullptr, t, N, 128);
    launch_gemm(256, false, buf2, Wroot3, nullptr, s, N, 128);
    launch_zero(agg, (long long)N * 128);
    launch_scatter(agg, t, eidx, E, 128);
    launch_combine(agg, s, b3, out, (long long)N * 128, 128);
}

// round 4
// speedup vs baseline: 2.2901x; 1.8638x over previous
#include <cuda_runtime.h>
#include <cuda_bf16.h>
#include <cstdint>

// ---------------------------------------------------------------------------
// SDNE graph autoencoder: 4x GraphConv (PyG) + leaky_relu(0.01).
//   layer: out = segsum(h[src]->dst) @ Wrel^T + b + h @ Wroot^T
// Linearity: aggregate in min(d_in, d_out) dim.
// Aggregation: CSR build (hist+scan+fill) then warp-per-node gather-sum.
// GEMM: mma.sync m16n8k16 bf16 hi/lo split (D += Ah*Bh + Ah*Bl + Al*Bh),
//   one launch per layer via K-concat / row-stacked pre-split weights.
// ---------------------------------------------------------------------------

#define NMAX  50000
#define EMAX  1000000
#define LEAKY 0.01f
typedef __nv_bfloat16 bf16;

// ------------------------------- scratch -----------------------------------
__device__ __align__(16) float g_buf [(size_t)NMAX * 256];
__device__ __align__(16) float g_t   [(size_t)NMAX * 128];
__device__ __align__(16) float g_s   [(size_t)NMAX * 128];
__device__ __align__(16) float g_agg [(size_t)NMAX * 128];
__device__ __align__(16) float g_emb [(size_t)NMAX * 64];
__device__ __align__(16) bf16  g_wh  [262144];
__device__ __align__(16) bf16  g_wl  [262144];
__device__ int g_rowptr[NMAX + 1];
__device__ int g_cnt   [2 * NMAX];     // [0..N) hist, [N..2N) fill cursor
__device__ int g_csr   [EMAX];
__device__ int g_tmp   [NMAX];
__device__ int g_bsum  [64];
__device__ int g_boff  [64];
__device__ int g_is64;

// --------------------------- helpers ----------------------------------------
__device__ __forceinline__ uint32_t smem_to_u32(const void* p) {
    uint32_t a;
    asm("{ .reg .u64 t; cvta.to.shared.u64 t, %1; cvt.u32.u64 %0, t; }"
        : "=r"(a) : "l"(p));
    return a;
}

#define LDSM4(r, addr) \
    asm volatile("ldmatrix.sync.aligned.m8n8.x4.shared.b16 {%0,%1,%2,%3}, [%4];" \
        : "=r"((r)[0]), "=r"((r)[1]), "=r"((r)[2]), "=r"((r)[3]) : "r"(addr))

#define MMA_BF16(c, a, b0r, b1r) \
    asm volatile("mma.sync.aligned.m16n8k16.row.col.f32.bf16.bf16.f32 " \
        "{%0,%1,%2,%3}, {%4,%5,%6,%7}, {%8,%9}, {%0,%1,%2,%3};" \
        : "+f"((c)[0]), "+f"((c)[1]), "+f"((c)[2]), "+f"((c)[3]) \
        : "r"((a)[0]), "r"((a)[1]), "r"((a)[2]), "r"((a)[3]), \
          "r"(b0r), "r"(b1r))

__device__ __forceinline__ void split2(float v0, float v1,
                                       uint32_t& h, uint32_t& l) {
    bf16 h0 = __float2bfloat16(v0), h1 = __float2bfloat16(v1);
    float r0 = v0 - __bfloat162float(h0);
    float r1 = v1 - __bfloat162float(h1);
    __nv_bfloat162 hh = __halves2bfloat162(h0, h1);
    __nv_bfloat162 ll = __halves2bfloat162(__float2bfloat16(r0),
                                           __float2bfloat16(r1));
    h = *(uint32_t*)&hh;
    l = *(uint32_t*)&ll;
}
__device__ __forceinline__ void split8(float4 a, float4 b, uint4& h, uint4& l) {
    split2(a.x, a.y, h.x, l.x);
    split2(a.z, a.w, h.y, l.y);
    split2(b.x, b.y, h.z, l.z);
    split2(b.z, b.w, h.w, l.w);
}

__device__ __forceinline__ void edge_pair(const void* eidx, int E, int e,
                                          int& src, int& dst) {
    if (g_is64) {
        const long long* p = (const long long*)eidx;
        src = (int)p[e]; dst = (int)p[E + e];
    } else {
        const int* p = (const int*)eidx;
        src = p[e]; dst = p[E + e];
    }
}

// --------------------------- CSR build --------------------------------------
__global__ void detect_idx64(const unsigned int* __restrict__ w, int npairs) {
    unsigned int any = 0;
    for (int k = threadIdx.x; k < npairs; k += blockDim.x)
        any |= w[2 * k + 1];
    unsigned int anynz = __syncthreads_or(any != 0u);
    if (threadIdx.x == 0) g_is64 = anynz ? 0 : 1;
}

__global__ void zero_int(int* __restrict__ p, int n) {
    int i = blockIdx.x * blockDim.x + threadIdx.x;
    if (i < n) p[i] = 0;
}

__global__ void hist_kernel(const void* __restrict__ eidx, int E) {
    int e = blockIdx.x * blockDim.x + threadIdx.x;
    if (e >= E) return;
    int src, dst;
    edge_pair(eidx, E, e, src, dst);
    atomicAdd(&g_cnt[dst], 1);
}

__global__ void scan_block(int n) {
    __shared__ int sm[1024];
    int i = blockIdx.x * 1024 + threadIdx.x;
    int v = (i < n) ? g_cnt[i] : 0;
    sm[threadIdx.x] = v;
    __syncthreads();
#pragma unroll
    for (int off = 1; off < 1024; off <<= 1) {
        int t = (threadIdx.x >= off) ? sm[threadIdx.x - off] : 0;
        __syncthreads();
        sm[threadIdx.x] += t;
        __syncthreads();
    }
    if (i < n) g_tmp[i] = sm[threadIdx.x];
    if (threadIdx.x == 1023) g_bsum[blockIdx.x] = sm[1023];
}

__global__ void scan_top(int nb) {
    if (threadIdx.x == 0) {
        int acc = 0;
        for (int k = 0; k < nb; k++) { g_boff[k] = acc; acc += g_bsum[k]; }
    }
}

__global__ void scan_add(int n) {
    int i = blockIdx.x * blockDim.x + threadIdx.x;
    if (i < n) g_rowptr[i + 1] = g_tmp[i] + g_boff[i >> 10];
    if (i == 0) g_rowptr[0] = 0;
}

__global__ void fill_kernel(const void* __restrict__ eidx, int E, int n) {
    int e = blockIdx.x * blockDim.x + threadIdx.x;
    if (e >= E) return;
    int src, dst;
    edge_pair(eidx, E, e, src, dst);
    int pos = atomicAdd(&g_cnt[n + dst], 1);
    g_csr[g_rowptr[dst] + pos] = src;
}

// ------------------------ warp-per-node aggregation --------------------------
// D = 128: float4/lane; D = 64: float2/lane.
// COMBINE: out = leaky(sum + s + b); else out = sum.
template <bool COMBINE>
__global__ void agg128_kernel(const float* __restrict__ feat,
                              float* __restrict__ outp,
                              const float* __restrict__ svec,
                              const float* __restrict__ bias, int n) {
    int node = (int)((blockIdx.x * (long long)blockDim.x + threadIdx.x) >> 5);
    int lane = threadIdx.x & 31;
    if (node >= n) return;
    int beg = g_rowptr[node], end = g_rowptr[node + 1];
    const int c = lane * 4;
    float4 acc = make_float4(0.f, 0.f, 0.f, 0.f);
    int e = beg;
    for (; e + 1 < end; e += 2) {
        int s0 = g_csr[e], s1 = g_csr[e + 1];
        float4 v0 = *(const float4*)(feat + (size_t)s0 * 128 + c);
        float4 v1 = *(const float4*)(feat + (size_t)s1 * 128 + c);
        acc.x += v0.x; acc.y += v0.y; acc.z += v0.z; acc.w += v0.w;
        acc.x += v1.x; acc.y += v1.y; acc.z += v1.z; acc.w += v1.w;
    }
    if (e < end) {
        float4 v0 = *(const float4*)(feat + (size_t)g_csr[e] * 128 + c);
        acc.x += v0.x; acc.y += v0.y; acc.z += v0.z; acc.w += v0.w;
    }
    float4 r = acc;
    if (COMBINE) {
        float4 sv = *(const float4*)(svec + (size_t)node * 128 + c);
        float4 bv = *(const float4*)(bias + c);
        r.x = acc.x + sv.x + bv.x; r.y = acc.y + sv.y + bv.y;
        r.z = acc.z + sv.z + bv.z; r.w = acc.w + sv.w + bv.w;
        r.x = (r.x > 0.f) ? r.x : LEAKY * r.x;
        r.y = (r.y > 0.f) ? r.y : LEAKY * r.y;
        r.z = (r.z > 0.f) ? r.z : LEAKY * r.z;
        r.w = (r.w > 0.f) ? r.w : LEAKY * r.w;
    }
    *(float4*)(outp + (size_t)node * 128 + c) = r;
}

template <bool COMBINE>
__global__ void agg64_kernel(const float* __restrict__ feat,
                             float* __restrict__ outp,
                             const float* __restrict__ svec,
                             const float* __restrict__ bias, int n) {
    int node = (int)((blockIdx.x * (long long)blockDim.x + threadIdx.x) >> 5);
    int lane = threadIdx.x & 31;
    if (node >= n) return;
    int beg = g_rowptr[node], end = g_rowptr[node + 1];
    const int c = lane * 2;
    float2 acc = make_float2(0.f, 0.f);
    int e = beg;
    for (; e + 1 < end; e += 2) {
        int s0 = g_csr[e], s1 = g_csr[e + 1];
        float2 v0 = *(const float2*)(feat + (size_t)s0 * 64 + c);
        float2 v1 = *(const float2*)(feat + (size_t)s1 * 64 + c);
        acc.x += v0.x; acc.y += v0.y;
        acc.x += v1.x; acc.y += v1.y;
    }
    if (e < end) {
        float2 v0 = *(const float2*)(feat + (size_t)g_csr[e] * 64 + c);
        acc.x += v0.x; acc.y += v0.y;
    }
    float2 r = acc;
    if (COMBINE) {
        float2 sv = *(const float2*)(svec + (size_t)node * 64 + c);
        float2 bv = *(const float2*)(bias + c);
        r.x = acc.x + sv.x + bv.x;
        r.y = acc.y + sv.y + bv.y;
        r.x = (r.x > 0.f) ? r.x : LEAKY * r.x;
        r.y = (r.y > 0.f) ? r.y : LEAKY * r.y;
    }
    *(float2*)(outp + (size_t)node * 64 + c) = r;
}

// --------------------------- weight pre-split --------------------------------
// g_wh/g_wl layout (bf16, contiguous):
//  [0,      65536): L0 cat:   256 rows x 256  (cols 0-127 Wrel0, 128-255 Wroot0)
//  [65536,  98304): L1 stack: 128 rows x 256  (rows 0-63 Wrel1, 64-127 Wroot1)
//  [98304, 131072): L2 cat:   256 rows x 128  (cols 0-63 Wrel2, 64-127 Wroot2)
//  [131072,196608): L3 stack: 256 rows x 256  (rows 0-127 Wrel3, 128-255 Wroot3)
struct WPtrs {
    const float *rel0, *root0, *rel1, *root1, *rel2, *root2, *rel3, *root3;
};
__global__ void wconv_kernel(WPtrs w, bf16* __restrict__ wh,
                             bf16* __restrict__ wl) {
    int i = blockIdx.x * blockDim.x + threadIdx.x;
    if (i >= 196608 / 8) return;
    int base = i * 8;
    const float* src;
    if (base < 65536) {
        int row = base >> 8, col = base & 255;
        src = (col < 128) ? w.rel0 + row * 128 + col
                          : w.root0 + row * 128 + (col - 128);
    } else if (base < 98304) {
        int j = base - 65536, row = j >> 8, col = j & 255;
        src = (row < 64) ? w.rel1 + row * 256 + col
                         : w.root1 + (row - 64) * 256 + col;
    } else if (base < 131072) {
        int j = base - 98304, row = j >> 7, col = j & 127;
        src = (col < 64) ? w.rel2 + row * 64 + col
                         : w.root2 + row * 64 + (col - 64);
    } else {
        int j = base - 131072, row = j >> 8, col = j & 255;
        src = (row < 128) ? w.rel3 + row * 256 + col
                          : w.root3 + (row - 128) * 256 + col;
    }
    float4 v0 = *(const float4*)src;
    float4 v1 = *(const float4*)(src + 4);
    uint4 h, l;
    split8(v0, v1, h, l);
    ((uint4*)wh)[i] = h;
    ((uint4*)wl)[i] = l;
}

// --------------------------- MMA GEMM ---------------------------------------
// C tile = A[M, K](fp32, split on the fly) @ W[*, K](bf16 pre-split)^T
// Block: 256 thr (8 warps 4x2), tile 128M x 64N, BK=64, chunk-xor swizzle.
struct GArgs {
    const float *a0, *a1;     // A sources (K-concat: chunks >= ksplit -> a1)
    int rl0, rl1;             // A row lengths (fp32 elems)
    int ksplit, nchunks;      // in 64-wide K chunks
    const bf16 *wh, *wl;      // pre-split W base
    int w_rl;                 // W row length (bf16 elems) = K total
    const float* bias;        // BIAS: +bias[gcol], leaky
    float *o0, *o1;           // outputs, split at column csplit
    int csplit, orl0, orl1;
    int M;
};

template <bool BIAS>
__global__ void __launch_bounds__(256) mma_gemm(GArgs g) {
    __shared__ __align__(16) unsigned char sm[49152];
    const int AH = 0, AL = 16384, WH = 32768, WL = 40960;
    const uint32_t sb = smem_to_u32(sm);

    const int tid  = threadIdx.x;
    const int lane = tid & 31;
    const int wid  = tid >> 5;
    const int wm   = wid >> 1;
    const int wn   = wid & 1;
    const int row0 = blockIdx.x * 128;
    const int col0 = blockIdx.y * 64;

    float acc[2][4][4];
#pragma unroll
    for (int i = 0; i < 2; i++)
#pragma unroll
        for (int j = 0; j < 4; j++)
#pragma unroll
            for (int q = 0; q < 4; q++) acc[i][j][q] = 0.0f;

    for (int kc = 0; kc < g.nchunks; kc++) {
        // ---- A tile fill: 128 rows x 64 cols fp32 -> bf16 hi/lo ----
        {
            const int row  = tid >> 1;
            const int grow = row0 + row;
            const bool ok  = grow < g.M;
            const bool kh  = kc >= g.ksplit;
            const float* ap = kh
                ? g.a1 + (size_t)grow * g.rl1 + (kc - g.ksplit) * 64
                : g.a0 + (size_t)grow * g.rl0 + kc * 64;
            ap += (tid & 1) * 32;
            const int rx = row & 7;
#pragma unroll
            for (int i = 0; i < 4; i++) {
                const int chunk = ((tid & 1) << 2) + i;
                float4 v0 = ok ? *(const float4*)(ap + i * 8)
                               : make_float4(0.f, 0.f, 0.f, 0.f);
                float4 v1 = ok ? *(const float4*)(ap + i * 8 + 4)
                               : make_float4(0.f, 0.f, 0.f, 0.f);
                uint4 h, l;
                split8(v0, v1, h, l);
                const uint32_t off = row * 128 + ((chunk ^ rx) << 4);
                *(uint4*)(sm + AH + off) = h;
                *(uint4*)(sm + AL + off) = l;
            }
        }
        // ---- W tile fill: 64 rows x 64 cols (bf16 copy) ----
        {
#pragma unroll
            for (int j = 0; j < 2; j++) {
                const int task  = tid * 2 + j;     // 0..511
                const int row   = task >> 3;
                const int chunk = task & 7;
                const size_t eo = (size_t)(col0 + row) * g.w_rl +
                                  kc * 64 + chunk * 8;
                uint4 h = *(const uint4*)(g.wh + eo);
                uint4 l = *(const uint4*)(g.wl + eo);
                const uint32_t off = row * 128 + ((chunk ^ (row & 7)) << 4);
                *(uint4*)(sm + WH + off) = h;
                *(uint4*)(sm + WL + off) = l;
            }
        }
        __syncthreads();

        // ---- compute: 4 k16 sub-steps ----
#pragma unroll
        for (int kk = 0; kk < 4; kk++) {
            uint32_t ah[2][4], al[2][4], bh[2][4], bl[2][4];
#pragma unroll
            for (int rb = 0; rb < 2; rb++) {
                const int row = wm * 32 + rb * 16 + (lane & 15);
                const int ch  = 2 * kk + (lane >> 4);
                const uint32_t ad = sb + AH + row * 128 +
                                    ((ch ^ (row & 7)) << 4);
                LDSM4(ah[rb], ad);
                LDSM4(al[rb], ad + 16384);
            }
#pragma unroll
            for (int q = 0; q < 2; q++) {
                const int sel  = lane >> 3;
                const int wrow = wn * 32 + q * 16 + ((sel >> 1) << 3) + (lane & 7);
                const int ch   = 2 * kk + (sel & 1);
                const uint32_t wd = sb + WH + wrow * 128 +
                                    ((ch ^ (wrow & 7)) << 4);
                LDSM4(bh[q], wd);
                LDSM4(bl[q], wd + 8192);
            }
#pragma unroll
            for (int rb = 0; rb < 2; rb++) {
#pragma unroll
                for (int nb = 0; nb < 4; nb++) {
                    const uint32_t b0h = bh[nb >> 1][(nb & 1) * 2];
                    const uint32_t b1h = bh[nb >> 1][(nb & 1) * 2 + 1];
                    const uint32_t b0l = bl[nb >> 1][(nb & 1) * 2];
                    const uint32_t b1l = bl[nb >> 1][(nb & 1) * 2 + 1];
                    MMA_BF16(acc[rb][nb], ah[rb], b0h, b1h);
                    MMA_BF16(acc[rb][nb], ah[rb], b0l, b1l);
                    MMA_BF16(acc[rb][nb], al[rb], b0h, b1h);
                }
            }
        }
        __syncthreads();
    }

    // ---- epilogue ----
    float* outp;
    int ocol0, orl;
    if (col0 < g.csplit) { outp = g.o0; ocol0 = col0; orl = g.orl0; }
    else { outp = g.o1; ocol0 = col0 - g.csplit; orl = g.orl1; }

    const int gr = lane >> 2;
    const int t4 = lane & 3;
#pragma unroll
    for (int rb = 0; rb < 2; rb++) {
        const int r1 = row0 + wm * 32 + rb * 16 + gr;
        const int r2 = r1 + 8;
#pragma unroll
        for (int nb = 0; nb < 4; nb++) {
            const int coff = wn * 32 + nb * 8 + t4 * 2;
            const float* ac = acc[rb][nb];
            float bb0 = 0.f, bb1 = 0.f;
            if (BIAS) {
                bb0 = g.bias[col0 + coff];
                bb1 = g.bias[col0 + coff + 1];
            }
            if (r1 < g.M) {
                float v0 = ac[0] + bb0, v1 = ac[1] + bb1;
                if (BIAS) {
                    v0 = (v0 > 0.f) ? v0 : LEAKY * v0;
                    v1 = (v1 > 0.f) ? v1 : LEAKY * v1;
                }
                *(float2*)(outp + (size_t)r1 * orl + ocol0 + coff) =
                    make_float2(v0, v1);
            }
            if (r2 < g.M) {
                float v0 = ac[2] + bb0, v1 = ac[3] + bb1;
                if (BIAS) {
                    v0 = (v0 > 0.f) ? v0 : LEAKY * v0;
                    v1 = (v1 > 0.f) ? v1 : LEAKY * v1;
                }
                *(float2*)(outp + (size_t)r2 * orl + ocol0 + coff) =
                    make_float2(v0, v1);
            }
        }
    }
}

// --------------------------- host side --------------------------------------
extern "C" void kernel_launch(void* const* d_in, const int* in_sizes, int n_in,
                              void* d_out, int out_size) {
    const float* x      = (const float*)d_in[0];
    const void*  eidx   = d_in[1];
    WPtrs w;
    w.rel0  = (const float*)d_in[2];
    w.root0 = (const float*)d_in[3];
    const float* b0 = (const float*)d_in[4];
    w.rel1  = (const float*)d_in[5];
    w.root1 = (const float*)d_in[6];
    const float* b1 = (const float*)d_in[7];
    w.rel2  = (const float*)d_in[8];
    w.root2 = (const float*)d_in[9];
    const float* b2 = (const float*)d_in[10];
    w.rel3  = (const float*)d_in[11];
    w.root3 = (const float*)d_in[12];
    const float* b3 = (const float*)d_in[13];

    const int N = in_sizes[0] / 128;
    const int E = in_sizes[1] / 2;
    float* out = (float*)d_out;

    float *buf, *t, *s, *agg, *embS;
    bf16 *wh, *wl;
    cudaGetSymbolAddress((void**)&buf,  g_buf);
    cudaGetSymbolAddress((void**)&t,    g_t);
    cudaGetSymbolAddress((void**)&s,    g_s);
    cudaGetSymbolAddress((void**)&agg,  g_agg);
    cudaGetSymbolAddress((void**)&embS, g_emb);
    cudaGetSymbolAddress((void**)&wh,   g_wh);
    cudaGetSymbolAddress((void**)&wl,   g_wl);
    int* cnt;
    cudaGetSymbolAddress((void**)&cnt, g_cnt);

    float* emb = ((long long)out_size >= (long long)N * 192)
                     ? out + (size_t)N * 128 : embS;

    // ---- setup: idx dtype, weight split, CSR build ----
    int npairs = E < 4096 ? E : 4096;
    detect_idx64<<<1, 256>>>((const unsigned int*)eidx, npairs);
    wconv_kernel<<<(196608 / 8 + 255) / 256, 256>>>(w, wh, wl);

    zero_int<<<(2 * N + 255) / 256, 256>>>(cnt, 2 * N);
    hist_kernel<<<(E + 255) / 256, 256>>>(eidx, E);
    const int nb = (N + 1023) / 1024;
    scan_block<<<nb, 1024>>>(N);
    scan_top<<<1, 32>>>(nb);
    scan_add<<<(N + 255) / 256, 256>>>(N);
    fill_kernel<<<(E + 255) / 256, 256>>>(eidx, E, N);

    const int MT = (N + 127) / 128;
    const int AGGB = (N * 32 + 255) / 256;   // warp per node, 8 warps/block

    // ---- Layer 0: agg = segsum(x); buf = leaky([agg||x] @ Wcat0^T + b0) ----
    agg128_kernel<false><<<AGGB, 256>>>(x, agg, nullptr, nullptr, N);
    {
        GArgs a = {};
        a.a0 = agg; a.a1 = x; a.rl0 = 128; a.rl1 = 128;
        a.ksplit = 2; a.nchunks = 4;
        a.wh = wh; a.wl = wl; a.w_rl = 256;
        a.bias = b0;
        a.o0 = buf; a.o1 = buf; a.csplit = 256; a.orl0 = 256; a.orl1 = 256;
        a.M = N;
        mma_gemm<true><<<dim3(MT, 4), 256>>>(a);
    }

    // ---- Layer 1: [t|s] = buf @ [Wrel1;Wroot1]^T; emb = leaky(seg(t)+s+b1) --
    {
        GArgs a = {};
        a.a0 = buf; a.a1 = buf; a.rl0 = 256; a.rl1 = 256;
        a.ksplit = 4; a.nchunks = 4;
        a.wh = wh + 65536; a.wl = wl + 65536; a.w_rl = 256;
        a.o0 = t; a.o1 = s; a.csplit = 64; a.orl0 = 64; a.orl1 = 64;
        a.M = N;
        mma_gemm<false><<<dim3(MT, 2), 256>>>(a);
    }
    agg64_kernel<true><<<AGGB, 256>>>(t, emb, s, b1, N);

    // ---- Layer 2: agg = segsum(emb); buf = leaky([agg||emb] @ Wcat2^T + b2) -
    agg64_kernel<false><<<AGGB, 256>>>(emb, agg, nullptr, nullptr, N);
    {
        GArgs a = {};
        a.a0 = agg; a.a1 = emb; a.rl0 = 64; a.rl1 = 64;
        a.ksplit = 1; a.nchunks = 2;
        a.wh = wh + 98304; a.wl = wl + 98304; a.w_rl = 128;
        a.bias = b2;
        a.o0 = buf; a.o1 = buf; a.csplit = 256; a.orl0 = 256; a.orl1 = 256;
        a.M = N;
        mma_gemm<true><<<dim3(MT, 4), 256>>>(a);
    }

    // ---- Layer 3: [t|s] = buf @ [Wrel3;Wroot3]^T; out = leaky(seg(t)+s+b3) --
    {
        GArgs a = {};
        a.a0 = buf; a.a1 = buf; a.rl0 = 256; a.rl1 = 256;
        a.ksplit = 4; a.nchunks = 4;
        a.wh = wh + 131072; a.wl = wl + 131072; a.w_rl = 256;
        a.o0 = t; a.o1 = s; a.csplit = 128; a.orl0 = 128; a.orl1 = 128;
        a.M = N;
        mma_gemm<false><<<dim3(MT, 4), 256>>>(a);
    }
    agg128_kernel<true><<<AGGB, 256>>>(t, out, s, b3, N);
}

// round 5
// speedup vs baseline: 2.9227x; 1.2763x over previous
#include <cuda_runtime.h>
#include <cuda_bf16.h>
#include <cstdint>

// ---------------------------------------------------------------------------
// SDNE graph autoencoder: 4x GraphConv (PyG) + leaky_relu(0.01).
//   layer: out = segsum(h[src]->dst) @ Wrel^T + b + h @ Wroot^T
// Linearity: aggregate in min(d_in, d_out) dim.
// Aggregation: CSR (hist+scan+fill) then warp-per-node gather-sum; epilogues
//   emit bf16 hi/lo splits so GEMM A-operands are always pre-split.
// GEMM: mma.sync m16n8k16 bf16 hi/lo split (D += Ah*Bh + Ah*Bl + Al*Bh),
//   cp.async double-buffered mainloop, one launch per layer.
// ---------------------------------------------------------------------------

#define NMAX  50000
#define EMAX  1000000
#define LEAKY 0.01f
typedef __nv_bfloat16 bf16;

// ------------------------------- scratch -----------------------------------
__device__ __align__(16) float g_t   [(size_t)NMAX * 128];
__device__ __align__(16) float g_s   [(size_t)NMAX * 128];
__device__ __align__(16) float g_emb [(size_t)NMAX * 64];
__device__ __align__(16) bf16  g_bufh[(size_t)NMAX * 256];
__device__ __align__(16) bf16  g_bufl[(size_t)NMAX * 256];
__device__ __align__(16) bf16  g_aggh[(size_t)NMAX * 128];
__device__ __align__(16) bf16  g_aggl[(size_t)NMAX * 128];
__device__ __align__(16) bf16  g_xh  [(size_t)NMAX * 128];
__device__ __align__(16) bf16  g_xl  [(size_t)NMAX * 128];
__device__ __align__(16) bf16  g_embh[(size_t)NMAX * 64];
__device__ __align__(16) bf16  g_embl[(size_t)NMAX * 64];
__device__ __align__(16) bf16  g_wh  [262144];
__device__ __align__(16) bf16  g_wl  [262144];
__device__ int g_rowptr[NMAX + 1];
__device__ int g_cnt   [2 * NMAX];
__device__ int g_csr   [EMAX];
__device__ int g_src   [EMAX];
__device__ int g_dst   [EMAX];
__device__ int g_tmp   [NMAX];
__device__ int g_bsum  [64];
__device__ int g_boff  [64];
__device__ int g_is64;

// --------------------------- helpers ----------------------------------------
__device__ __forceinline__ uint32_t smem_to_u32(const void* p) {
    uint32_t a;
    asm("{ .reg .u64 t; cvta.to.shared.u64 t, %1; cvt.u32.u64 %0, t; }"
        : "=r"(a) : "l"(p));
    return a;
}

#define LDSM4(r, addr) \
    asm volatile("ldmatrix.sync.aligned.m8n8.x4.shared.b16 {%0,%1,%2,%3}, [%4];" \
        : "=r"((r)[0]), "=r"((r)[1]), "=r"((r)[2]), "=r"((r)[3]) : "r"(addr))

#define MMA_BF16(c, a, b0r, b1r) \
    asm volatile("mma.sync.aligned.m16n8k16.row.col.f32.bf16.bf16.f32 " \
        "{%0,%1,%2,%3}, {%4,%5,%6,%7}, {%8,%9}, {%0,%1,%2,%3};" \
        : "+f"((c)[0]), "+f"((c)[1]), "+f"((c)[2]), "+f"((c)[3]) \
        : "r"((a)[0]), "r"((a)[1]), "r"((a)[2]), "r"((a)[3]), \
          "r"(b0r), "r"(b1r))

#define CP16(dst, src, sz) \
    asm volatile("cp.async.cg.shared.global [%0], [%1], 16, %2;" \
        :: "r"(dst), "l"(src), "r"(sz) : "memory")
#define CP_COMMIT() asm volatile("cp.async.commit_group;" ::: "memory")
#define CP_WAIT0()  asm volatile("cp.async.wait_group 0;" ::: "memory")
#define CP_WAIT1()  asm volatile("cp.async.wait_group 1;" ::: "memory")

__device__ __forceinline__ void split2(float v0, float v1,
                                       uint32_t& h, uint32_t& l) {
    bf16 h0 = __float2bfloat16(v0), h1 = __float2bfloat16(v1);
    float r0 = v0 - __bfloat162float(h0);
    float r1 = v1 - __bfloat162float(h1);
    __nv_bfloat162 hh = __halves2bfloat162(h0, h1);
    __nv_bfloat162 ll = __halves2bfloat162(__float2bfloat16(r0),
                                           __float2bfloat16(r1));
    h = *(uint32_t*)&hh;
    l = *(uint32_t*)&ll;
}
__device__ __forceinline__ void split8(float4 a, float4 b, uint4& h, uint4& l) {
    split2(a.x, a.y, h.x, l.x);
    split2(a.z, a.w, h.y, l.y);
    split2(b.x, b.y, h.z, l.z);
    split2(b.z, b.w, h.w, l.w);
}

// --------------------------- CSR build --------------------------------------
__global__ void detect_idx64(const unsigned int* __restrict__ w, int npairs) {
    unsigned int any = 0;
    for (int k = threadIdx.x; k < npairs; k += blockDim.x)
        any |= w[2 * k + 1];
    unsigned int anynz = __syncthreads_or(any != 0u);
    if (threadIdx.x == 0) g_is64 = anynz ? 0 : 1;
}

// decode edges to int32, zero counters, histogram of dst
__global__ void econv_hist(const void* __restrict__ eidx, int E, int n) {
    int e = blockIdx.x * blockDim.x + threadIdx.x;
    if (e < 2 * n) g_cnt[e] = 0;
    if (e >= E) return;
    int src, dst;
    if (g_is64) {
        const long long* p = (const long long*)eidx;
        src = (int)p[e]; dst = (int)p[E + e];
    } else {
        const int* p = (const int*)eidx;
        src = p[e]; dst = p[E + e];
    }
    g_src[e] = src;
    g_dst[e] = dst;
}

__global__ void hist_kernel(int E) {
    int e = blockIdx.x * blockDim.x + threadIdx.x;
    if (e < E) atomicAdd(&g_cnt[g_dst[e]], 1);
}

__global__ void scan_block(int n) {
    __shared__ int sm[1024];
    int i = blockIdx.x * 1024 + threadIdx.x;
    int v = (i < n) ? g_cnt[i] : 0;
    sm[threadIdx.x] = v;
    __syncthreads();
#pragma unroll
    for (int off = 1; off < 1024; off <<= 1) {
        int t = (threadIdx.x >= off) ? sm[threadIdx.x - off] : 0;
        __syncthreads();
        sm[threadIdx.x] += t;
        __syncthreads();
    }
    if (i < n) g_tmp[i] = sm[threadIdx.x];
    if (threadIdx.x == 1023) g_bsum[blockIdx.x] = sm[1023];
}

__global__ void scan_top(int nb) {
    if (threadIdx.x == 0) {
        int acc = 0;
        for (int k = 0; k < nb; k++) { g_boff[k] = acc; acc += g_bsum[k]; }
    }
}

__global__ void scan_add(int n) {
    int i = blockIdx.x * blockDim.x + threadIdx.x;
    if (i < n) g_rowptr[i + 1] = g_tmp[i] + g_boff[i >> 10];
    if (i == 0) g_rowptr[0] = 0;
}

__global__ void fill_kernel(int E, int n) {
    int e = blockIdx.x * blockDim.x + threadIdx.x;
    if (e >= E) return;
    int dst = g_dst[e];
    int pos = atomicAdd(&g_cnt[n + dst], 1);
    g_csr[g_rowptr[dst] + pos] = g_src[e];
}

// ------------------------ warp-per-node aggregation --------------------------
// MODE: 0 = write bf16 hi/lo split only (GEMM A input)
//       1 = out fp32 = leaky(sum + s + b)                       (final layer)
//       2 = MODE1 + also write bf16 hi/lo split                 (emb layer)
template <int MODE>
__global__ void agg128_kernel(const float* __restrict__ feat,
                              float* __restrict__ outp,
                              bf16* __restrict__ oh, bf16* __restrict__ ol,
                              const float* __restrict__ svec,
                              const float* __restrict__ bias, int n) {
    int node = (int)((blockIdx.x * (long long)blockDim.x + threadIdx.x) >> 5);
    int lane = threadIdx.x & 31;
    if (node >= n) return;
    int beg = g_rowptr[node], end = g_rowptr[node + 1];
    const int c = lane * 4;
    float4 acc = make_float4(0.f, 0.f, 0.f, 0.f);
    int e = beg;
    for (; e + 1 < end; e += 2) {
        int s0 = g_csr[e], s1 = g_csr[e + 1];
        float4 v0 = *(const float4*)(feat + (size_t)s0 * 128 + c);
        float4 v1 = *(const float4*)(feat + (size_t)s1 * 128 + c);
        acc.x += v0.x; acc.y += v0.y; acc.z += v0.z; acc.w += v0.w;
        acc.x += v1.x; acc.y += v1.y; acc.z += v1.z; acc.w += v1.w;
    }
    if (e < end) {
        float4 v0 = *(const float4*)(feat + (size_t)g_csr[e] * 128 + c);
        acc.x += v0.x; acc.y += v0.y; acc.z += v0.z; acc.w += v0.w;
    }
    float4 r = acc;
    if (MODE >= 1) {
        float4 sv = *(const float4*)(svec + (size_t)node * 128 + c);
        float4 bv = *(const float4*)(bias + c);
        r.x = acc.x + sv.x + bv.x; r.y = acc.y + sv.y + bv.y;
        r.z = acc.z + sv.z + bv.z; r.w = acc.w + sv.w + bv.w;
        r.x = (r.x > 0.f) ? r.x : LEAKY * r.x;
        r.y = (r.y > 0.f) ? r.y : LEAKY * r.y;
        r.z = (r.z > 0.f) ? r.z : LEAKY * r.z;
        r.w = (r.w > 0.f) ? r.w : LEAKY * r.w;
        *(float4*)(outp + (size_t)node * 128 + c) = r;
    }
    if (MODE != 1) {
        uint32_t h0, l0, h1, l1;
        split2(r.x, r.y, h0, l0);
        split2(r.z, r.w, h1, l1);
        *(uint2*)(oh + (size_t)node * 128 + c) = make_uint2(h0, h1);
        *(uint2*)(ol + (size_t)node * 128 + c) = make_uint2(l0, l1);
    }
}

template <int MODE>
__global__ void agg64_kernel(const float* __restrict__ feat,
                             float* __restrict__ outp,
                             bf16* __restrict__ oh, bf16* __restrict__ ol,
                             const float* __restrict__ svec,
                             const float* __restrict__ bias, int n) {
    int node = (int)((blockIdx.x * (long long)blockDim.x + threadIdx.x) >> 5);
    int lane = threadIdx.x & 31;
    if (node >= n) return;
    int beg = g_rowptr[node], end = g_rowptr[node + 1];
    const int c = lane * 2;
    float2 acc = make_float2(0.f, 0.f);
    int e = beg;
    for (; e + 1 < end; e += 2) {
        int s0 = g_csr[e], s1 = g_csr[e + 1];
        float2 v0 = *(const float2*)(feat + (size_t)s0 * 64 + c);
        float2 v1 = *(const float2*)(feat + (size_t)s1 * 64 + c);
        acc.x += v0.x; acc.y += v0.y;
        acc.x += v1.x; acc.y += v1.y;
    }
    if (e < end) {
        float2 v0 = *(const float2*)(feat + (size_t)g_csr[e] * 64 + c);
        acc.x += v0.x; acc.y += v0.y;
    }
    float2 r = acc;
    if (MODE >= 1) {
        float2 sv = *(const float2*)(svec + (size_t)node * 64 + c);
        float2 bv = *(const float2*)(bias + c);
        r.x = acc.x + sv.x + bv.x;
        r.y = acc.y + sv.y + bv.y;
        r.x = (r.x > 0.f) ? r.x : LEAKY * r.x;
        r.y = (r.y > 0.f) ? r.y : LEAKY * r.y;
        *(float2*)(outp + (size_t)node * 64 + c) = r;
    }
    if (MODE != 1) {
        uint32_t h0, l0;
        split2(r.x, r.y, h0, l0);
        *(uint32_t*)(oh + (size_t)node * 64 + c) = h0;
        *(uint32_t*)(ol + (size_t)node * 64 + c) = l0;
    }
}

// fp32 -> (hi, lo) bf16 split for x
__global__ void cvt_split(const float* __restrict__ in,
                          bf16* __restrict__ hi, bf16* __restrict__ lo,
                          long long n8) {
    long long i = (long long)blockIdx.x * blockDim.x + threadIdx.x;
    if (i >= n8) return;
    const float4* p = (const float4*)in + i * 2;
    uint4 h, l;
    split8(p[0], p[1], h, l);
    ((uint4*)hi)[i] = h;
    ((uint4*)lo)[i] = l;
}

// --------------------------- weight pre-split --------------------------------
//  [0,      65536): L0 cat:   256 x 256  (cols 0-127 Wrel0, 128-255 Wroot0)
//  [65536,  98304): L1 stack: 128 x 256  (rows 0-63 Wrel1, 64-127 Wroot1)
//  [98304, 131072): L2 cat:   256 x 128  (cols 0-63 Wrel2, 64-127 Wroot2)
//  [131072,196608): L3 stack: 256 x 256  (rows 0-127 Wrel3, 128-255 Wroot3)
struct WPtrs {
    const float *rel0, *root0, *rel1, *root1, *rel2, *root2, *rel3, *root3;
};
__global__ void wconv_kernel(WPtrs w, bf16* __restrict__ wh,
                             bf16* __restrict__ wl) {
    int i = blockIdx.x * blockDim.x + threadIdx.x;
    if (i >= 196608 / 8) return;
    int base = i * 8;
    const float* src;
    if (base < 65536) {
        int row = base >> 8, col = base & 255;
        src = (col < 128) ? w.rel0 + row * 128 + col
                          : w.root0 + row * 128 + (col - 128);
    } else if (base < 98304) {
        int j = base - 65536, row = j >> 8, col = j & 255;
        src = (row < 64) ? w.rel1 + row * 256 + col
                         : w.root1 + (row - 64) * 256 + col;
    } else if (base < 131072) {
        int j = base - 98304, row = j >> 7, col = j & 127;
        src = (col < 64) ? w.rel2 + row * 64 + col
                         : w.root2 + row * 64 + (col - 64);
    } else {
        int j = base - 131072, row = j >> 8, col = j & 255;
        src = (row < 128) ? w.rel3 + row * 256 + col
                          : w.root3 + (row - 128) * 256 + col;
    }
    float4 v0 = *(const float4*)src;
    float4 v1 = *(const float4*)(src + 4);
    uint4 h, l;
    split8(v0, v1, h, l);
    ((uint4*)wh)[i] = h;
    ((uint4*)wl)[i] = l;
}

// --------------------------- MMA GEMM ---------------------------------------
// C tile = A[M, K](bf16 pre-split) @ W[*, K](bf16 pre-split)^T
// Block: 256 thr (8 warps 4x2), tile 128M x 64N, BK=64, chunk-xor swizzle,
// 2-stage cp.async pipeline (stage = 48KB: A hi 16K, A lo 16K, W hi 8K, W lo 8K).
struct GArgs {
    const bf16 *a0h, *a0l, *a1h, *a1l;   // A sources (chunks >= ksplit -> a1)
    int rl0, rl1;                        // A row lengths (bf16 elems)
    int ksplit, nchunks;                 // 64-wide K chunks
    const bf16 *wh, *wl;                 // pre-split W base
    int w_rl;                            // W row length = K total
    const float* bias;                   // BIAS mode
    bf16 *oh, *ol; int orl;              // BIAS out (bf16 split)
    float *o0, *o1;                      // !BIAS out, split at column csplit
    int csplit, orl0, orl1;
    int M;
};

#define STAGE_BYTES 49152

template <bool BIAS>
__global__ void __launch_bounds__(256) mma_gemm(GArgs g) {
    extern __shared__ __align__(16) unsigned char sm[];
    const uint32_t sb = smem_to_u32(sm);

    const int tid  = threadIdx.x;
    const int lane = tid & 31;
    const int wid  = tid >> 5;
    const int wm   = wid >> 1;
    const int wn   = wid & 1;
    const int row0 = blockIdx.x * 128;
    const int col0 = blockIdx.y * 64;

    // per-thread prefetch constants
    const int arow  = tid >> 1;
    const int agrow = row0 + arow;
    const uint32_t asz = (agrow < g.M) ? 16u : 0u;
    const int arx = arow & 7;

    float acc[2][4][4];
#pragma unroll
    for (int i = 0; i < 2; i++)
#pragma unroll
        for (int j = 0; j < 4; j++)
#pragma unroll
            for (int q = 0; q < 4; q++) acc[i][j][q] = 0.0f;

#define PREFETCH(kc, st) do {                                                 \
        const uint32_t base = sb + (st) * STAGE_BYTES;                        \
        const bool kh = (kc) >= g.ksplit;                                     \
        const bf16* ah = kh ? g.a1h : g.a0h;                                  \
        const bf16* al = kh ? g.a1l : g.a0l;                                  \
        const int rl = kh ? g.rl1 : g.rl0;                                    \
        const size_t eo = (size_t)agrow * rl +                                \
                          (size_t)((kh ? (kc) - g.ksplit : (kc)) * 64) +      \
                          ((tid & 1) << 5);                                   \
        _Pragma("unroll")                                                     \
        for (int i2 = 0; i2 < 4; i2++) {                                      \
            const int chunk = ((tid & 1) << 2) + i2;                          \
            const uint32_t off = arow * 128 + ((chunk ^ arx) << 4);           \
            CP16(base + off,         ah + eo + i2 * 8, asz);                  \
            CP16(base + 16384 + off, al + eo + i2 * 8, asz);                  \
        }                                                                     \
        _Pragma("unroll")                                                     \
        for (int j2 = 0; j2 < 2; j2++) {                                      \
            const int task = tid * 2 + j2;                                    \
            const int wrow = task >> 3, wch = task & 7;                       \
            const size_t we = (size_t)(col0 + wrow) * g.w_rl +                \
                              (size_t)(kc) * 64 + wch * 8;                    \
            const uint32_t off = wrow * 128 + ((wch ^ (wrow & 7)) << 4);      \
            CP16(base + 32768 + off, g.wh + we, 16u);                         \
            CP16(base + 40960 + off, g.wl + we, 16u);                         \
        }                                                                     \
        CP_COMMIT();                                                          \
    } while (0)

    PREFETCH(0, 0);
    if (g.nchunks > 1) PREFETCH(1, 1);

    for (int c = 0; c < g.nchunks; c++) {
        if (c + 1 < g.nchunks) CP_WAIT1(); else CP_WAIT0();
        __syncthreads();
        const uint32_t base = sb + (c & 1) * STAGE_BYTES;

#pragma unroll
        for (int kk = 0; kk < 4; kk++) {
            uint32_t ah[2][4], al[2][4], bh[2][4], bl[2][4];
#pragma unroll
            for (int rb = 0; rb < 2; rb++) {
                const int row = wm * 32 + rb * 16 + (lane & 15);
                const int ch  = 2 * kk + (lane >> 4);
                const uint32_t ad = base + row * 128 +
                                    ((ch ^ (row & 7)) << 4);
                LDSM4(ah[rb], ad);
                LDSM4(al[rb], ad + 16384);
            }
#pragma unroll
            for (int q = 0; q < 2; q++) {
                const int sel  = lane >> 3;
                const int wrow = wn * 32 + q * 16 + ((sel >> 1) << 3) + (lane & 7);
                const int ch   = 2 * kk + (sel & 1);
                const uint32_t wd = base + 32768 + wrow * 128 +
                                    ((ch ^ (wrow & 7)) << 4);
                LDSM4(bh[q], wd);
                LDSM4(bl[q], wd + 8192);
            }
#pragma unroll
            for (int rb = 0; rb < 2; rb++) {
#pragma unroll
                for (int nb = 0; nb < 4; nb++) {
                    const uint32_t b0h = bh[nb >> 1][(nb & 1) * 2];
                    const uint32_t b1h = bh[nb >> 1][(nb & 1) * 2 + 1];
                    const uint32_t b0l = bl[nb >> 1][(nb & 1) * 2];
                    const uint32_t b1l = bl[nb >> 1][(nb & 1) * 2 + 1];
                    MMA_BF16(acc[rb][nb], ah[rb], b0h, b1h);
                    MMA_BF16(acc[rb][nb], ah[rb], b0l, b1l);
                    MMA_BF16(acc[rb][nb], al[rb], b0h, b1h);
                }
            }
        }
        __syncthreads();
        if (c + 2 < g.nchunks) PREFETCH(c + 2, c & 1);
    }

    // ---- epilogue ----
    const int gr = lane >> 2;
    const int t4 = lane & 3;

    if (BIAS) {
#pragma unroll
        for (int rb = 0; rb < 2; rb++) {
            const int r1 = row0 + wm * 32 + rb * 16 + gr;
            const int r2 = r1 + 8;
#pragma unroll
            for (int nb = 0; nb < 4; nb++) {
                const int col = col0 + wn * 32 + nb * 8 + t4 * 2;
                const float* ac = acc[rb][nb];
                const float bb0 = g.bias[col], bb1 = g.bias[col + 1];
                if (r1 < g.M) {
                    float v0 = ac[0] + bb0, v1 = ac[1] + bb1;
                    v0 = (v0 > 0.f) ? v0 : LEAKY * v0;
                    v1 = (v1 > 0.f) ? v1 : LEAKY * v1;
                    uint32_t h, l;
                    split2(v0, v1, h, l);
                    *(uint32_t*)(g.oh + (size_t)r1 * g.orl + col) = h;
                    *(uint32_t*)(g.ol + (size_t)r1 * g.orl + col) = l;
                }
                if (r2 < g.M) {
                    float v0 = ac[2] + bb0, v1 = ac[3] + bb1;
                    v0 = (v0 > 0.f) ? v0 : LEAKY * v0;
                    v1 = (v1 > 0.f) ? v1 : LEAKY * v1;
                    uint32_t h, l;
                    split2(v0, v1, h, l);
                    *(uint32_t*)(g.oh + (size_t)r2 * g.orl + col) = h;
                    *(uint32_t*)(g.ol + (size_t)r2 * g.orl + col) = l;
                }
            }
        }
    } else {
        float* outp;
        int ocol0, orl;
        if (col0 < g.csplit) { outp = g.o0; ocol0 = col0; orl = g.orl0; }
        else { outp = g.o1; ocol0 = col0 - g.csplit; orl = g.orl1; }
#pragma unroll
        for (int rb = 0; rb < 2; rb++) {
            const int r1 = row0 + wm * 32 + rb * 16 + gr;
            const int r2 = r1 + 8;
#pragma unroll
            for (int nb = 0; nb < 4; nb++) {
                const int coff = wn * 32 + nb * 8 + t4 * 2;
                const float* ac = acc[rb][nb];
                if (r1 < g.M)
                    *(float2*)(outp + (size_t)r1 * orl + ocol0 + coff) =
                        make_float2(ac[0], ac[1]);
                if (r2 < g.M)
                    *(float2*)(outp + (size_t)r2 * orl + ocol0 + coff) =
                        make_float2(ac[2], ac[3]);
            }
        }
    }
#undef PREFETCH
}

// --------------------------- host side --------------------------------------
extern "C" void kernel_launch(void* const* d_in, const int* in_sizes, int n_in,
                              void* d_out, int out_size) {
    const float* x    = (const float*)d_in[0];
    const void*  eidx = d_in[1];
    WPtrs w;
    w.rel0  = (const float*)d_in[2];
    w.root0 = (const float*)d_in[3];
    const float* b0 = (const float*)d_in[4];
    w.rel1  = (const float*)d_in[5];
    w.root1 = (const float*)d_in[6];
    const float* b1 = (const float*)d_in[7];
    w.rel2  = (const float*)d_in[8];
    w.root2 = (const float*)d_in[9];
    const float* b2 = (const float*)d_in[10];
    w.rel3  = (const float*)d_in[11];
    w.root3 = (const float*)d_in[12];
    const float* b3 = (const float*)d_in[13];

    const int N = in_sizes[0] / 128;
    const int E = in_sizes[1] / 2;
    float* out = (float*)d_out;

    float *t, *s, *embS;
    bf16 *bufh, *bufl, *aggh, *aggl, *xh, *xl, *embh, *embl, *wh, *wl;
    cudaGetSymbolAddress((void**)&t,    g_t);
    cudaGetSymbolAddress((void**)&s,    g_s);
    cudaGetSymbolAddress((void**)&embS, g_emb);
    cudaGetSymbolAddress((void**)&bufh, g_bufh);
    cudaGetSymbolAddress((void**)&bufl, g_bufl);
    cudaGetSymbolAddress((void**)&aggh, g_aggh);
    cudaGetSymbolAddress((void**)&aggl, g_aggl);
    cudaGetSymbolAddress((void**)&xh,   g_xh);
    cudaGetSymbolAddress((void**)&xl,   g_xl);
    cudaGetSymbolAddress((void**)&embh, g_embh);
    cudaGetSymbolAddress((void**)&embl, g_embl);
    cudaGetSymbolAddress((void**)&wh,   g_wh);
    cudaGetSymbolAddress((void**)&wl,   g_wl);

    float* emb = ((long long)out_size >= (long long)N * 192)
                     ? out + (size_t)N * 128 : embS;

    static bool attr_done = false;
    if (!attr_done) {
        cudaFuncSetAttribute(mma_gemm<true>,
            cudaFuncAttributeMaxDynamicSharedMemorySize, 2 * STAGE_BYTES);
        cudaFuncSetAttribute(mma_gemm<false>,
            cudaFuncAttributeMaxDynamicSharedMemorySize, 2 * STAGE_BYTES);
        attr_done = true;
    }

    // ---- setup: idx dtype, weight split, x split, CSR build ----
    int npairs = E < 4096 ? E : 4096;
    detect_idx64<<<1, 256>>>((const unsigned int*)eidx, npairs);
    wconv_kernel<<<(196608 / 8 + 255) / 256, 256>>>(w, wh, wl);
    cvt_split<<<(int)(((long long)N * 16 + 255) / 256), 256>>>(
        x, xh, xl, (long long)N * 16);

    int ec_n = (E > 2 * N) ? E : 2 * N;
    econv_hist<<<(ec_n + 255) / 256, 256>>>(eidx, E, N);
    hist_kernel<<<(E + 255) / 256, 256>>>(E);
    const int nb = (N + 1023) / 1024;
    scan_block<<<nb, 1024>>>(N);
    scan_top<<<1, 32>>>(nb);
    scan_add<<<(N + 255) / 256, 256>>>(N);
    fill_kernel<<<(E + 255) / 256, 256>>>(E, N);

    const int MT = (N + 127) / 128;
    const int AGGB = (N * 32 + 255) / 256;

    // ---- Layer 0: agg = segsum(x) (split); buf = leaky([agg||x]@W0^T+b0) ----
    agg128_kernel<0><<<AGGB, 256>>>(x, nullptr, aggh, aggl, nullptr, nullptr, N);
    {
        GArgs a = {};
        a.a0h = aggh; a.a0l = aggl; a.a1h = xh; a.a1l = xl;
        a.rl0 = 128; a.rl1 = 128; a.ksplit = 2; a.nchunks = 4;
        a.wh = wh; a.wl = wl; a.w_rl = 256;
        a.bias = b0; a.oh = bufh; a.ol = bufl; a.orl = 256; a.M = N;
        mma_gemm<true><<<dim3(MT, 4), 256, 2 * STAGE_BYTES>>>(a);
    }

    // ---- Layer 1: [t|s] = buf @ [Wrel1;Wroot1]^T; emb = leaky(seg(t)+s+b1) --
    {
        GArgs a = {};
        a.a0h = bufh; a.a0l = bufl; a.a1h = bufh; a.a1l = bufl;
        a.rl0 = 256; a.rl1 = 256; a.ksplit = 4; a.nchunks = 4;
        a.wh = wh + 65536; a.wl = wl + 65536; a.w_rl = 256;
        a.o0 = t; a.o1 = s; a.csplit = 64; a.orl0 = 64; a.orl1 = 64; a.M = N;
        mma_gemm<false><<<dim3(MT, 2), 256, 2 * STAGE_BYTES>>>(a);
    }
    agg64_kernel<2><<<AGGB, 256>>>(t, emb, embh, embl, s, b1, N);

    // ---- Layer 2: agg = segsum(emb) (split); buf = leaky([agg||emb]@W2^T+b2)
    agg64_kernel<0><<<AGGB, 256>>>(emb, nullptr, aggh, aggl, nullptr, nullptr, N);
    {
        GArgs a = {};
        a.a0h = aggh; a.a0l = aggl; a.a1h = embh; a.a1l = embl;
        a.rl0 = 64; a.rl1 = 64; a.ksplit = 1; a.nchunks = 2;
        a.wh = wh + 98304; a.wl = wl + 98304; a.w_rl = 128;
        a.bias = b2; a.oh = bufh; a.ol = bufl; a.orl = 256; a.M = N;
        mma_gemm<true><<<dim3(MT, 4), 256, 2 * STAGE_BYTES>>>(a);
    }

    // ---- Layer 3: [t|s] = buf @ [Wrel3;Wroot3]^T; out = leaky(seg(t)+s+b3) --
    {
        GArgs a = {};
        a.a0h = bufh; a.a0l = bufl; a.a1h = bufh; a.a1l = bufl;
        a.rl0 = 256; a.rl1 = 256; a.ksplit = 4; a.nchunks = 4;
        a.wh = wh + 131072; a.wl = wl + 131072; a.w_rl = 256;
        a.o0 = t; a.o1 = s; a.csplit = 128; a.orl0 = 128; a.orl1 = 128; a.M = N;
        mma_gemm<false><<<dim3(MT, 4), 256, 2 * STAGE_BYTES>>>(a);
    }
    agg128_kernel<1><<<AGGB, 256>>>(t, out, nullptr, nullptr, s, b3, N);
}